// round 7
// baseline (speedup 1.0000x reference)
#include <cuda_runtime.h>
#include <cuda_bf16.h>
#include <cstdint>

// ============================================================================
// 2-layer LSTM (H=32, T=7, F=1) + fc(H,1) + fc1(T,1), B=262144.
// R7: TWO-PHASE split. Kernel A runs layer 0 for all t (h0 -> gmem scratch),
// kernel B runs layer 1 + output reduction. Each phase holds half the SMEM
// state -> 13 / 12 warps per SM (vs 10 fused) for latency hiding.
// E=2 elems/thread, broadcast LDS.128 weights (4x) + 1 LDS.64 h per k-iter
// feeding 16 FFMA2 (f32x2). c0 in regs (A), c1 in gmem (B).
// ============================================================================

typedef unsigned long long u64;

#define NTA 416          // kernel A threads (13 warps)
#define NTB 384          // kernel B threads (12 warps)
#define NPMAX 262144ull  // max element-pairs supported

// h0 scratch: [t][unit][pair] packed (hA,hB). 470MB static.
__device__ u64 g_h0[7ull * 32ull * NPMAX];
// layer-1 cell scratch: row = 2*unit_pair + elem (32 rows), col = pair.
__device__ u64 g_c1[32ull * NPMAX];

__device__ __forceinline__ u64 pk2(float lo, float hi) {
    u64 r; asm("mov.b64 %0,{%1,%2};" : "=l"(r) : "f"(lo), "f"(hi)); return r;
}
__device__ __forceinline__ u64 bc2(float v) { return pk2(v, v); }
__device__ __forceinline__ void upk2(u64 v, float& lo, float& hi) {
    asm("mov.b64 {%0,%1},%2;" : "=f"(lo), "=f"(hi) : "l"(v));
}
__device__ __forceinline__ u64 fma2(u64 a, u64 b, u64 c) {
    u64 d; asm("fma.rn.f32x2 %0,%1,%2,%3;" : "=l"(d) : "l"(a), "l"(b), "l"(c)); return d;
}
__device__ __forceinline__ u64 mul2(u64 a, u64 b) {
    u64 d; asm("mul.rn.f32x2 %0,%1,%2;" : "=l"(d) : "l"(a), "l"(b)); return d;
}
__device__ __forceinline__ float ex2f(float x) {
    float y; asm("ex2.approx.f32 %0,%1;" : "=f"(y) : "f"(x)); return y;
}
__device__ __forceinline__ float rcpf(float x) {
    float y; asm("rcp.approx.f32 %0,%1;" : "=f"(y) : "f"(x)); return y;
}
__device__ __forceinline__ float fsig(float x) {
    float e = ex2f(-1.4426950408889634f * x);
    return rcpf(1.0f + e);
}
__device__ __forceinline__ float ftanhx(float x) {
    float t = fminf(-2.8853900817779268f * x, 120.0f);
    float e = ex2f(t);
    float r = rcpf(1.0f + e);
    return fmaf(-e, r, r);
}
__device__ __forceinline__ u64 sig2(u64 z) {
    float a, b; upk2(z, a, b); return pk2(fsig(a), fsig(b));
}
__device__ __forceinline__ u64 tanh2(u64 z) {
    float a, b; upk2(z, a, b); return pk2(ftanhx(a), ftanhx(b));
}

template <bool DOACC>
__device__ __forceinline__ u64 lstm_upd(
    u64 zi, u64 zf, u64 zg, u64 zo, u64& c, u64 wo, u64& acc)
{
    u64 i2 = sig2(zi);
    u64 f2 = sig2(zf);
    u64 g2 = tanh2(zg);
    u64 o2 = sig2(zo);
    c = fma2(f2, c, mul2(i2, g2));
    u64 h2 = mul2(o2, tanh2(c));
    if (DOACC) acc = fma2(h2, wo, acc);
    return h2;
}

// ---------------- kernel A: layer 0, all timesteps ----------------
// SMEM: WL0 2048 + B0 64 + WI0 64 + H0A 32*NTA + H0B 32*NTA  (u64)
#define SMEM_A_U64 (2048 + 64 + 64 + 64 * NTA)
#define SMEM_A_BYTES (SMEM_A_U64 * 8)

extern "C" __global__ void __launch_bounds__(NTA, 1)
lstm_l0_kernel(const float* __restrict__ x,
               const float* __restrict__ Wih0, const float* __restrict__ Whh0,
               const float* __restrict__ bih0, const float* __restrict__ bhh0,
               int NP)
{
    extern __shared__ u64 sm[];
    u64* WL0 = sm;
    u64* B0  = WL0 + 2048;
    u64* WI0 = B0 + 64;
    u64* H0A = WI0 + 64;
    u64* H0B = H0A + 32 * NTA;
    const int tid = threadIdx.x;

    // repack Whh0: WL0[((c*32+k)*8)+s], s -> gate g=s>>1, sub=s&1,
    // rows r0 = g*32 + 4c + 2*sub, r0+1; col k. (validated mapping)
    for (int d = tid; d < 2048; d += NTA) {
        int c = d >> 8, k = (d >> 3) & 31, s = d & 7;
        int g = s >> 1, sub = s & 1;
        int r0 = g * 32 + 4 * c + 2 * sub;
        WL0[d] = pk2(Whh0[r0 * 32 + k], Whh0[(r0 + 1) * 32 + k]);
    }
    if (tid < 128) {
        ((float*)B0)[tid]  = bih0[tid] + bhh0[tid];
        ((float*)WI0)[tid] = Wih0[tid];
    }
#pragma unroll
    for (int u = 0; u < 32; u++) { H0A[u * NTA + tid] = 0ull; H0B[u * NTA + tid] = 0ull; }
    __syncthreads();

    const long long pid = (long long)blockIdx.x * NTA + tid;
    if (pid >= NP) return;
    const long long eA = 2 * pid;

    float xa[7], xb[7];
#pragma unroll
    for (int t = 0; t < 7; t++) { xa[t] = x[eA * 7 + t]; xb[t] = x[eA * 7 + 7 + t]; }

    u64 ca[16], cb[16];
#pragma unroll
    for (int p = 0; p < 16; p++) { ca[p] = 0ull; cb[p] = 0ull; }
    u64 dmy = 0ull;

#pragma unroll 1
    for (int t = 0; t < 7; t++) {
        u64* Hrd = (t & 1) ? H0B : H0A;
        u64* Hwr = (t & 1) ? H0A : H0B;
        u64 x2a = bc2(xa[t]), x2b = bc2(xb[t]);

#pragma unroll
        for (int c = 0; c < 8; c++) {
            const int p0 = 2 * c;
            u64 wi0 = WI0[p0],      wi1 = WI0[p0 + 1];
            u64 wf0 = WI0[p0 + 16], wf1 = WI0[p0 + 17];
            u64 wg0 = WI0[p0 + 32], wg1 = WI0[p0 + 33];
            u64 wo0 = WI0[p0 + 48], wo1 = WI0[p0 + 49];
            u64 zai0 = fma2(x2a, wi0, B0[p0]),      zbi0 = fma2(x2b, wi0, B0[p0]);
            u64 zai1 = fma2(x2a, wi1, B0[p0 + 1]),  zbi1 = fma2(x2b, wi1, B0[p0 + 1]);
            u64 zaf0 = fma2(x2a, wf0, B0[p0 + 16]), zbf0 = fma2(x2b, wf0, B0[p0 + 16]);
            u64 zaf1 = fma2(x2a, wf1, B0[p0 + 17]), zbf1 = fma2(x2b, wf1, B0[p0 + 17]);
            u64 zag0 = fma2(x2a, wg0, B0[p0 + 32]), zbg0 = fma2(x2b, wg0, B0[p0 + 32]);
            u64 zag1 = fma2(x2a, wg1, B0[p0 + 33]), zbg1 = fma2(x2b, wg1, B0[p0 + 33]);
            u64 zao0 = fma2(x2a, wo0, B0[p0 + 48]), zbo0 = fma2(x2b, wo0, B0[p0 + 48]);
            u64 zao1 = fma2(x2a, wo1, B0[p0 + 49]), zbo1 = fma2(x2b, wo1, B0[p0 + 49]);

            const ulonglong2* wp = (const ulonglong2*)(WL0 + (size_t)c * 256);
#pragma unroll 2
            for (int k = 0; k < 32; k++) {
                ulonglong2 q0 = wp[4 * k + 0];
                ulonglong2 q1 = wp[4 * k + 1];
                ulonglong2 q2 = wp[4 * k + 2];
                ulonglong2 q3 = wp[4 * k + 3];
                float ha, hb; upk2(Hrd[k * NTA + tid], ha, hb);
                u64 hka = bc2(ha), hkb = bc2(hb);
                zai0 = fma2(hka, q0.x, zai0); zbi0 = fma2(hkb, q0.x, zbi0);
                zai1 = fma2(hka, q0.y, zai1); zbi1 = fma2(hkb, q0.y, zbi1);
                zaf0 = fma2(hka, q1.x, zaf0); zbf0 = fma2(hkb, q1.x, zbf0);
                zaf1 = fma2(hka, q1.y, zaf1); zbf1 = fma2(hkb, q1.y, zbf1);
                zag0 = fma2(hka, q2.x, zag0); zbg0 = fma2(hkb, q2.x, zbg0);
                zag1 = fma2(hka, q2.y, zag1); zbg1 = fma2(hkb, q2.y, zbg1);
                zao0 = fma2(hka, q3.x, zao0); zbo0 = fma2(hkb, q3.x, zbo0);
                zao1 = fma2(hka, q3.y, zao1); zbo1 = fma2(hkb, q3.y, zbo1);
            }
            u64 h2a0 = lstm_upd<false>(zai0, zaf0, zag0, zao0, ca[p0],     0ull, dmy);
            u64 h2b0 = lstm_upd<false>(zbi0, zbf0, zbg0, zbo0, cb[p0],     0ull, dmy);
            u64 h2a1 = lstm_upd<false>(zai1, zaf1, zag1, zao1, ca[p0 + 1], 0ull, dmy);
            u64 h2b1 = lstm_upd<false>(zbi1, zbf1, zbg1, zbo1, cb[p0 + 1], 0ull, dmy);

            float a0, a1, b0v, b1v;
            upk2(h2a0, a0, a1); upk2(h2b0, b0v, b1v);
            u64 hn0 = pk2(a0, b0v), hn1 = pk2(a1, b1v);
            upk2(h2a1, a0, a1); upk2(h2b1, b0v, b1v);
            u64 hn2 = pk2(a0, b0v), hn3 = pk2(a1, b1v);

            Hwr[(4 * c + 0) * NTA + tid] = hn0;
            Hwr[(4 * c + 1) * NTA + tid] = hn1;
            Hwr[(4 * c + 2) * NTA + tid] = hn2;
            Hwr[(4 * c + 3) * NTA + tid] = hn3;
            long long gb = (long long)(t * 32 + 4 * c) * NP + pid;
            g_h0[gb]               = hn0;
            g_h0[gb + NP]          = hn1;
            g_h0[gb + 2LL * NP]    = hn2;
            g_h0[gb + 3LL * NP]    = hn3;
        }
    }
}

// ---------------- kernel B: layer 1 + output ----------------
// SMEM: WLX1 2048 + WLH1 2048 + B1 64 + WO 112 + H0IN 32*NTB + H1 32*NTB
#define SMEM_B_U64 (2048 + 2048 + 64 + 112 + 64 * NTB)
#define SMEM_B_BYTES (SMEM_B_U64 * 8)

extern "C" __global__ void __launch_bounds__(NTB, 1)
lstm_l1_kernel(const float* __restrict__ Wih1, const float* __restrict__ Whh1,
               const float* __restrict__ bih1, const float* __restrict__ bhh1,
               const float* __restrict__ fcw,  const float* __restrict__ fcb,
               const float* __restrict__ fc1w, const float* __restrict__ fc1b,
               float* __restrict__ out, int NP)
{
    extern __shared__ u64 sm[];
    u64* WLX1 = sm;
    u64* WLH1 = WLX1 + 2048;
    u64* B1   = WLH1 + 2048;
    u64* WO   = B1 + 64;
    u64* H0IN = WO + 112;
    u64* H1   = H0IN + 32 * NTB;
    const int tid = threadIdx.x;

    for (int d = tid; d < 2048; d += NTB) {
        int c = d >> 8, k = (d >> 3) & 31, s = d & 7;
        int g = s >> 1, sub = s & 1;
        int r0 = g * 32 + 4 * c + 2 * sub;
        WLX1[d] = pk2(Wih1[r0 * 32 + k], Wih1[(r0 + 1) * 32 + k]);
        WLH1[d] = pk2(Whh1[r0 * 32 + k], Whh1[(r0 + 1) * 32 + k]);
    }
    if (tid < 128) {
        ((float*)B1)[tid] = bih1[tid] + bhh1[tid];
    }
    {
        float* WOf = (float*)WO;
        for (int d = tid; d < 224; d += NTB) WOf[d] = fc1w[d >> 5] * fcw[d & 31];
    }
#pragma unroll
    for (int u = 0; u < 32; u++) H1[u * NTB + tid] = 0ull;
    __syncthreads();

    const long long pid = (long long)blockIdx.x * NTB + tid;
    if (pid >= NP) return;

    u64 acca = 0ull, accb = 0ull;

#pragma unroll 1
    for (int t = 0; t < 7; t++) {
        // stream this step's h0 into per-thread SMEM slots
        {
            const u64* gsrc = g_h0 + (long long)(t * 32) * NP + pid;
#pragma unroll
            for (int u = 0; u < 32; u++) H0IN[u * NTB + tid] = gsrc[(long long)u * NP];
        }

        u64 hn[32];
#pragma unroll
        for (int c = 0; c < 8; c++) {
            const int p0 = 2 * c;
            // prefetch c1 from gmem scratch (zeros at t==0)
            u64 ca0 = 0ull, cb0 = 0ull, ca1 = 0ull, cb1 = 0ull;
            u64* crow = g_c1 + (long long)(2 * p0) * NP + pid;
            if (t) {
                ca0 = crow[0];
                cb0 = crow[(long long)NP];
                ca1 = crow[2LL * NP];
                cb1 = crow[3LL * NP];
            }

            u64 zai0 = B1[p0],      zai1 = B1[p0 + 1];
            u64 zaf0 = B1[p0 + 16], zaf1 = B1[p0 + 17];
            u64 zag0 = B1[p0 + 32], zag1 = B1[p0 + 33];
            u64 zao0 = B1[p0 + 48], zao1 = B1[p0 + 49];
            u64 zbi0 = zai0, zbi1 = zai1;
            u64 zbf0 = zaf0, zbf1 = zaf1;
            u64 zbg0 = zag0, zbg1 = zag1;
            u64 zbo0 = zao0, zbo1 = zao1;

            {
                const ulonglong2* wp = (const ulonglong2*)(WLX1 + (size_t)c * 256);
#pragma unroll 2
                for (int k = 0; k < 32; k++) {
                    ulonglong2 q0 = wp[4 * k + 0];
                    ulonglong2 q1 = wp[4 * k + 1];
                    ulonglong2 q2 = wp[4 * k + 2];
                    ulonglong2 q3 = wp[4 * k + 3];
                    float ha, hb; upk2(H0IN[k * NTB + tid], ha, hb);
                    u64 hka = bc2(ha), hkb = bc2(hb);
                    zai0 = fma2(hka, q0.x, zai0); zbi0 = fma2(hkb, q0.x, zbi0);
                    zai1 = fma2(hka, q0.y, zai1); zbi1 = fma2(hkb, q0.y, zbi1);
                    zaf0 = fma2(hka, q1.x, zaf0); zbf0 = fma2(hkb, q1.x, zbf0);
                    zaf1 = fma2(hka, q1.y, zaf1); zbf1 = fma2(hkb, q1.y, zbf1);
                    zag0 = fma2(hka, q2.x, zag0); zbg0 = fma2(hkb, q2.x, zbg0);
                    zag1 = fma2(hka, q2.y, zag1); zbg1 = fma2(hkb, q2.y, zbg1);
                    zao0 = fma2(hka, q3.x, zao0); zbo0 = fma2(hkb, q3.x, zbo0);
                    zao1 = fma2(hka, q3.y, zao1); zbo1 = fma2(hkb, q3.y, zbo1);
                }
            }
            {
                const ulonglong2* wp = (const ulonglong2*)(WLH1 + (size_t)c * 256);
#pragma unroll 2
                for (int k = 0; k < 32; k++) {
                    ulonglong2 q0 = wp[4 * k + 0];
                    ulonglong2 q1 = wp[4 * k + 1];
                    ulonglong2 q2 = wp[4 * k + 2];
                    ulonglong2 q3 = wp[4 * k + 3];
                    float ha, hb; upk2(H1[k * NTB + tid], ha, hb);
                    u64 hka = bc2(ha), hkb = bc2(hb);
                    zai0 = fma2(hka, q0.x, zai0); zbi0 = fma2(hkb, q0.x, zbi0);
                    zai1 = fma2(hka, q0.y, zai1); zbi1 = fma2(hkb, q0.y, zbi1);
                    zaf0 = fma2(hka, q1.x, zaf0); zbf0 = fma2(hkb, q1.x, zbf0);
                    zaf1 = fma2(hka, q1.y, zaf1); zbf1 = fma2(hkb, q1.y, zbf1);
                    zag0 = fma2(hka, q2.x, zag0); zbg0 = fma2(hkb, q2.x, zbg0);
                    zag1 = fma2(hka, q2.y, zag1); zbg1 = fma2(hkb, q2.y, zbg1);
                    zao0 = fma2(hka, q3.x, zao0); zbo0 = fma2(hkb, q3.x, zbo0);
                    zao1 = fma2(hka, q3.y, zao1); zbo1 = fma2(hkb, q3.y, zbo1);
                }
            }
            u64 wo_p0 = WO[t * 16 + p0], wo_p1 = WO[t * 16 + p0 + 1];
            u64 h2a0 = lstm_upd<true>(zai0, zaf0, zag0, zao0, ca0, wo_p0, acca);
            u64 h2b0 = lstm_upd<true>(zbi0, zbf0, zbg0, zbo0, cb0, wo_p0, accb);
            u64 h2a1 = lstm_upd<true>(zai1, zaf1, zag1, zao1, ca1, wo_p1, acca);
            u64 h2b1 = lstm_upd<true>(zbi1, zbf1, zbg1, zbo1, cb1, wo_p1, accb);
            if (t < 6) {
                crow[0]          = ca0;
                crow[(long long)NP] = cb0;
                crow[2LL * NP]   = ca1;
                crow[3LL * NP]   = cb1;
            }
            float a0, a1, b0v, b1v;
            upk2(h2a0, a0, a1); upk2(h2b0, b0v, b1v);
            hn[4 * c + 0] = pk2(a0, b0v); hn[4 * c + 1] = pk2(a1, b1v);
            upk2(h2a1, a0, a1); upk2(h2b1, b0v, b1v);
            hn[4 * c + 2] = pk2(a0, b0v); hn[4 * c + 3] = pk2(a1, b1v);
        }
#pragma unroll
        for (int u = 0; u < 32; u++) H1[u * NTB + tid] = hn[u];
    }

    float s = 0.0f;
#pragma unroll
    for (int t = 0; t < 7; t++) s += fc1w[t];
    float bias = fcb[0] * s + fc1b[0];

    float alo, ahi; upk2(acca, alo, ahi);
    float blo, bhi; upk2(accb, blo, bhi);
    float2 res;
    res.x = alo + ahi + bias;
    res.y = blo + bhi + bias;
    reinterpret_cast<float2*>(out)[pid] = res;
}

extern "C" void kernel_launch(void* const* d_in, const int* in_sizes, int n_in,
                              void* d_out, int out_size) {
    const float* x    = (const float*)d_in[0];
    const float* Wih0 = (const float*)d_in[1];
    const float* Whh0 = (const float*)d_in[2];
    const float* bih0 = (const float*)d_in[3];
    const float* bhh0 = (const float*)d_in[4];
    const float* Wih1 = (const float*)d_in[5];
    const float* Whh1 = (const float*)d_in[6];
    const float* bih1 = (const float*)d_in[7];
    const float* bhh1 = (const float*)d_in[8];
    const float* fcw  = (const float*)d_in[9];
    const float* fcb  = (const float*)d_in[10];
    const float* fc1w = (const float*)d_in[11];
    const float* fc1b = (const float*)d_in[12];
    float* out = (float*)d_out;

    const int B = in_sizes[0] / 7;  // [B, T=7, F=1]; B is even (262144)
    const int NP = B / 2;           // element pairs

    cudaFuncSetAttribute(lstm_l0_kernel,
                         cudaFuncAttributeMaxDynamicSharedMemorySize, SMEM_A_BYTES);
    cudaFuncSetAttribute(lstm_l1_kernel,
                         cudaFuncAttributeMaxDynamicSharedMemorySize, SMEM_B_BYTES);

    int gridA = (NP + NTA - 1) / NTA;
    int gridB = (NP + NTB - 1) / NTB;

    lstm_l0_kernel<<<gridA, NTA, SMEM_A_BYTES>>>(x, Wih0, Whh0, bih0, bhh0, NP);
    lstm_l1_kernel<<<gridB, NTB, SMEM_B_BYTES>>>(Wih1, Whh1, bih1, bhh1,
                                                 fcw, fcb, fc1w, fc1b, out, NP);
}

// round 10
// speedup vs baseline: 1.2313x; 1.2313x over previous
#include <cuda_runtime.h>
#include <cuda_bf16.h>
#include <cstdint>

// ============================================================================
// 2-layer LSTM (H=32, T=7, F=1) + fc(H,1) + fc1(T,1), B=262144.
// R9 = R6 (best: 1348us) with k-loop unroll 2 -> 8 for deep LDS MLP
// (R3's full-unroll hid latency at L1=89.6%; R6's unroll-2 only 55.9%).
// E=2 elems/thread, broadcast LDS.128 weights + 1 LDS.64 h per k-iter
// feeding 16 FFMA2 (f32x2). c-state in __device__ gmem scratch, h in SMEM,
// h-new staged in regs. NT=320 (10 warps/SM), SMEM 215KB, ~180 regs.
// ============================================================================

typedef unsigned long long u64;

#define NT 320          // threads per CTA (10 warps)
#define EPC (2 * NT)    // batch elements per CTA
#define BMAX 524288ull  // scratch capacity (>= B)

// c-state scratch: row r = layer*16 + unit_pair (32 rows), column = element id.
__device__ u64 g_cstate[32ull * BMAX];

__device__ __forceinline__ u64 pk2(float lo, float hi) {
    u64 r; asm("mov.b64 %0,{%1,%2};" : "=l"(r) : "f"(lo), "f"(hi)); return r;
}
__device__ __forceinline__ u64 bc2(float v) { return pk2(v, v); }
__device__ __forceinline__ void upk2(u64 v, float& lo, float& hi) {
    asm("mov.b64 {%0,%1},%2;" : "=f"(lo), "=f"(hi) : "l"(v));
}
__device__ __forceinline__ u64 fma2(u64 a, u64 b, u64 c) {
    u64 d; asm("fma.rn.f32x2 %0,%1,%2,%3;" : "=l"(d) : "l"(a), "l"(b), "l"(c)); return d;
}
__device__ __forceinline__ u64 mul2(u64 a, u64 b) {
    u64 d; asm("mul.rn.f32x2 %0,%1,%2;" : "=l"(d) : "l"(a), "l"(b)); return d;
}
__device__ __forceinline__ float ex2f(float x) {
    float y; asm("ex2.approx.f32 %0,%1;" : "=f"(y) : "f"(x)); return y;
}
__device__ __forceinline__ float rcpf(float x) {
    float y; asm("rcp.approx.f32 %0,%1;" : "=f"(y) : "f"(x)); return y;
}
__device__ __forceinline__ float fsig(float x) {
    float e = ex2f(-1.4426950408889634f * x);
    return rcpf(1.0f + e);
}
__device__ __forceinline__ float ftanhx(float x) {
    float t = fminf(-2.8853900817779268f * x, 120.0f);
    float e = ex2f(t);
    float r = rcpf(1.0f + e);
    return fmaf(-e, r, r);
}
__device__ __forceinline__ u64 sig2(u64 z) {
    float a, b; upk2(z, a, b); return pk2(fsig(a), fsig(b));
}
__device__ __forceinline__ u64 tanh2(u64 z) {
    float a, b; upk2(z, a, b); return pk2(ftanhx(a), ftanhx(b));
}

template <bool DOACC>
__device__ __forceinline__ u64 lstm_upd(
    u64 zi, u64 zf, u64 zg, u64 zo, u64& c, u64 wo, u64& acc)
{
    u64 i2 = sig2(zi);
    u64 f2 = sig2(zf);
    u64 g2 = tanh2(zg);
    u64 o2 = sig2(zo);
    c = fma2(f2, c, mul2(i2, g2));
    u64 h2 = mul2(o2, tanh2(c));
    if (DOACC) acc = fma2(h2, wo, acc);
    return h2;
}

// SMEM layout (u64 units):
//  WL0  [8c][32k][8s] repacked Whh0   2048
//  WLX1 [8c][32k][8s] repacked Wih1   2048
//  WLH1 [8c][32k][8s] repacked Whh1   2048
//  B0   [64]  (b_ih0+b_hh0) pairs       64
//  WI0  [64]  W_ih0[:,0] pairs          64
//  B1   [64]  (b_ih1+b_hh1) pairs       64
//  WO   [7][16] fc1_w[t]*fc_w pairs    112
//  H0   [32k][320t]  (hA,hB) packed  10240
//  H1   [32k][320t]  (hA,hB) packed  10240
// total = 26928 u64 = 215424 B
#define SMEM_U64S 26928
#define SMEM_BYTES (SMEM_U64S * 8)

extern "C" __global__ void __launch_bounds__(NT, 1)
lstm_b262144_kernel(
    const float* __restrict__ x,
    const float* __restrict__ Wih0, const float* __restrict__ Whh0,
    const float* __restrict__ bih0, const float* __restrict__ bhh0,
    const float* __restrict__ Wih1, const float* __restrict__ Whh1,
    const float* __restrict__ bih1, const float* __restrict__ bhh1,
    const float* __restrict__ fcw,  const float* __restrict__ fcb,
    const float* __restrict__ fc1w, const float* __restrict__ fc1b,
    float* __restrict__ out, int B)
{
    extern __shared__ u64 sm[];
    u64* WL0  = sm;
    u64* WLX1 = WL0 + 2048;
    u64* WLH1 = WLX1 + 2048;
    u64* B0   = WLH1 + 2048;
    u64* WI0  = B0 + 64;
    u64* B1   = WI0 + 64;
    u64* WO   = B1 + 64;
    u64* H0   = WO + 112;
    u64* H1   = H0 + 32 * NT;

    const int tid = threadIdx.x;

    // ---- repack weights: WL[((c*32+k)*8)+s], s -> gate g=s>>1, sub=s&1,
    // rows r0 = g*32 + 4c + 2*sub, r0+1; col k. (validated mapping) ----
    for (int d = tid; d < 2048; d += NT) {
        int c = d >> 8, k = (d >> 3) & 31, s = d & 7;
        int g = s >> 1, sub = s & 1;
        int r0 = g * 32 + 4 * c + 2 * sub;
        WL0[d]  = pk2(Whh0[r0 * 32 + k], Whh0[(r0 + 1) * 32 + k]);
        WLX1[d] = pk2(Wih1[r0 * 32 + k], Wih1[(r0 + 1) * 32 + k]);
        WLH1[d] = pk2(Whh1[r0 * 32 + k], Whh1[(r0 + 1) * 32 + k]);
    }
    if (tid < 128) {
        ((float*)B0)[tid]  = bih0[tid] + bhh0[tid];
        ((float*)WI0)[tid] = Wih0[tid];
        ((float*)B1)[tid]  = bih1[tid] + bhh1[tid];
    }
    {
        float* WOf = (float*)WO;
        for (int d = tid; d < 224; d += NT) WOf[d] = fc1w[d >> 5] * fcw[d & 31];
    }
    // zero h-state (own slots only)
#pragma unroll
    for (int u = 0; u < 32; u++) {
        H0[u * NT + tid] = 0ull;
        H1[u * NT + tid] = 0ull;
    }
    __syncthreads();

    const long long Bll = B;
    const long long eA = (long long)blockIdx.x * EPC + tid;
    if (eA >= Bll) return;
    const long long eB = eA + NT;
    const bool storeB = (eB < Bll);
    const long long eBs = storeB ? eB : eA;  // clamp (duplicate compute)

    float xa[7], xb[7];
#pragma unroll
    for (int t = 0; t < 7; t++) { xa[t] = x[eA * 7 + t]; xb[t] = x[eBs * 7 + t]; }

    u64 hn[32];          // h-new staging: per-unit (hA,hB); reused by both layers
    u64 acca = 0ull, accb = 0ull;
    u64 dmy = 0ull;

#pragma unroll 1
    for (int t = 0; t < 7; t++) {
        u64 x2a = bc2(xa[t]), x2b = bc2(xb[t]);

        // ========================= layer 0 =========================
#pragma unroll
        for (int c = 0; c < 8; c++) {
            const int p0 = 2 * c;
            // prefetch c-state (zeros at t==0)
            u64 ca0 = 0ull, cb0 = 0ull, ca1 = 0ull, cb1 = 0ull;
            u64* r0 = g_cstate + (u64)p0 * BMAX;
            u64* r1 = g_cstate + (u64)(p0 + 1) * BMAX;
            if (t) {
                ca0 = r0[eA]; cb0 = r0[eBs];
                ca1 = r1[eA]; cb1 = r1[eBs];
            }

            // x-projection init (weights/biases broadcast from SMEM)
            u64 wi0 = WI0[p0], wi1 = WI0[p0 + 1];
            u64 wf0 = WI0[p0 + 16], wf1 = WI0[p0 + 17];
            u64 wg0 = WI0[p0 + 32], wg1 = WI0[p0 + 33];
            u64 wo0 = WI0[p0 + 48], wo1 = WI0[p0 + 49];
            u64 zai0 = fma2(x2a, wi0, B0[p0]),      zbi0 = fma2(x2b, wi0, B0[p0]);
            u64 zai1 = fma2(x2a, wi1, B0[p0 + 1]),  zbi1 = fma2(x2b, wi1, B0[p0 + 1]);
            u64 zaf0 = fma2(x2a, wf0, B0[p0 + 16]), zbf0 = fma2(x2b, wf0, B0[p0 + 16]);
            u64 zaf1 = fma2(x2a, wf1, B0[p0 + 17]), zbf1 = fma2(x2b, wf1, B0[p0 + 17]);
            u64 zag0 = fma2(x2a, wg0, B0[p0 + 32]), zbg0 = fma2(x2b, wg0, B0[p0 + 32]);
            u64 zag1 = fma2(x2a, wg1, B0[p0 + 33]), zbg1 = fma2(x2b, wg1, B0[p0 + 33]);
            u64 zao0 = fma2(x2a, wo0, B0[p0 + 48]), zbo0 = fma2(x2b, wo0, B0[p0 + 48]);
            u64 zao1 = fma2(x2a, wo1, B0[p0 + 49]), zbo1 = fma2(x2b, wo1, B0[p0 + 49]);

            const ulonglong2* wp = (const ulonglong2*)(WL0 + (size_t)c * 256);
#pragma unroll 8
            for (int k = 0; k < 32; k++) {
                ulonglong2 q0 = wp[4 * k + 0];
                ulonglong2 q1 = wp[4 * k + 1];
                ulonglong2 q2 = wp[4 * k + 2];
                ulonglong2 q3 = wp[4 * k + 3];
                float ha, hb; upk2(H0[k * NT + tid], ha, hb);
                u64 hka = bc2(ha), hkb = bc2(hb);
                zai0 = fma2(hka, q0.x, zai0); zbi0 = fma2(hkb, q0.x, zbi0);
                zai1 = fma2(hka, q0.y, zai1); zbi1 = fma2(hkb, q0.y, zbi1);
                zaf0 = fma2(hka, q1.x, zaf0); zbf0 = fma2(hkb, q1.x, zbf0);
                zaf1 = fma2(hka, q1.y, zaf1); zbf1 = fma2(hkb, q1.y, zbf1);
                zag0 = fma2(hka, q2.x, zag0); zbg0 = fma2(hkb, q2.x, zbg0);
                zag1 = fma2(hka, q2.y, zag1); zbg1 = fma2(hkb, q2.y, zbg1);
                zao0 = fma2(hka, q3.x, zao0); zbo0 = fma2(hkb, q3.x, zbo0);
                zao1 = fma2(hka, q3.y, zao1); zbo1 = fma2(hkb, q3.y, zbo1);
            }
            u64 h2a0 = lstm_upd<false>(zai0, zaf0, zag0, zao0, ca0, 0ull, dmy);
            u64 h2b0 = lstm_upd<false>(zbi0, zbf0, zbg0, zbo0, cb0, 0ull, dmy);
            u64 h2a1 = lstm_upd<false>(zai1, zaf1, zag1, zao1, ca1, 0ull, dmy);
            u64 h2b1 = lstm_upd<false>(zbi1, zbf1, zbg1, zbo1, cb1, 0ull, dmy);
            if (t < 6) {
                r0[eA] = ca0; r0[eBs] = cb0;
                r1[eA] = ca1; r1[eBs] = cb1;
            }
            float a0, a1, b0v, b1v;
            upk2(h2a0, a0, a1); upk2(h2b0, b0v, b1v);
            hn[4 * c + 0] = pk2(a0, b0v); hn[4 * c + 1] = pk2(a1, b1v);
            upk2(h2a1, a0, a1); upk2(h2b1, b0v, b1v);
            hn[4 * c + 2] = pk2(a0, b0v); hn[4 * c + 3] = pk2(a1, b1v);
        }
        // publish new h0 (all reads of old h0 done; own slots only)
#pragma unroll
        for (int u = 0; u < 32; u++) H0[u * NT + tid] = hn[u];

        // ========================= layer 1 =========================
#pragma unroll
        for (int c = 0; c < 8; c++) {
            const int p0 = 2 * c;
            u64 ca0 = 0ull, cb0 = 0ull, ca1 = 0ull, cb1 = 0ull;
            u64* r0 = g_cstate + (u64)(16 + p0) * BMAX;
            u64* r1 = g_cstate + (u64)(16 + p0 + 1) * BMAX;
            if (t) {
                ca0 = r0[eA]; cb0 = r0[eBs];
                ca1 = r1[eA]; cb1 = r1[eBs];
            }

            u64 zai0 = B1[p0],      zai1 = B1[p0 + 1];
            u64 zaf0 = B1[p0 + 16], zaf1 = B1[p0 + 17];
            u64 zag0 = B1[p0 + 32], zag1 = B1[p0 + 33];
            u64 zao0 = B1[p0 + 48], zao1 = B1[p0 + 49];
            u64 zbi0 = zai0, zbi1 = zai1;
            u64 zbf0 = zaf0, zbf1 = zaf1;
            u64 zbg0 = zag0, zbg1 = zag1;
            u64 zbo0 = zao0, zbo1 = zao1;

            {
                const ulonglong2* wp = (const ulonglong2*)(WLX1 + (size_t)c * 256);
#pragma unroll 8
                for (int k = 0; k < 32; k++) {
                    ulonglong2 q0 = wp[4 * k + 0];
                    ulonglong2 q1 = wp[4 * k + 1];
                    ulonglong2 q2 = wp[4 * k + 2];
                    ulonglong2 q3 = wp[4 * k + 3];
                    float ha, hb; upk2(H0[k * NT + tid], ha, hb);
                    u64 hka = bc2(ha), hkb = bc2(hb);
                    zai0 = fma2(hka, q0.x, zai0); zbi0 = fma2(hkb, q0.x, zbi0);
                    zai1 = fma2(hka, q0.y, zai1); zbi1 = fma2(hkb, q0.y, zbi1);
                    zaf0 = fma2(hka, q1.x, zaf0); zbf0 = fma2(hkb, q1.x, zbf0);
                    zaf1 = fma2(hka, q1.y, zaf1); zbf1 = fma2(hkb, q1.y, zbf1);
                    zag0 = fma2(hka, q2.x, zag0); zbg0 = fma2(hkb, q2.x, zbg0);
                    zag1 = fma2(hka, q2.y, zag1); zbg1 = fma2(hkb, q2.y, zbg1);
                    zao0 = fma2(hka, q3.x, zao0); zbo0 = fma2(hkb, q3.x, zbo0);
                    zao1 = fma2(hka, q3.y, zao1); zbo1 = fma2(hkb, q3.y, zbo1);
                }
            }
            {
                const ulonglong2* wp = (const ulonglong2*)(WLH1 + (size_t)c * 256);
#pragma unroll 8
                for (int k = 0; k < 32; k++) {
                    ulonglong2 q0 = wp[4 * k + 0];
                    ulonglong2 q1 = wp[4 * k + 1];
                    ulonglong2 q2 = wp[4 * k + 2];
                    ulonglong2 q3 = wp[4 * k + 3];
                    float ha, hb; upk2(H1[k * NT + tid], ha, hb);
                    u64 hka = bc2(ha), hkb = bc2(hb);
                    zai0 = fma2(hka, q0.x, zai0); zbi0 = fma2(hkb, q0.x, zbi0);
                    zai1 = fma2(hka, q0.y, zai1); zbi1 = fma2(hkb, q0.y, zbi1);
                    zaf0 = fma2(hka, q1.x, zaf0); zbf0 = fma2(hkb, q1.x, zbf0);
                    zaf1 = fma2(hka, q1.y, zaf1); zbf1 = fma2(hkb, q1.y, zbf1);
                    zag0 = fma2(hka, q2.x, zag0); zbg0 = fma2(hkb, q2.x, zbg0);
                    zag1 = fma2(hka, q2.y, zag1); zbg1 = fma2(hkb, q2.y, zbg1);
                    zao0 = fma2(hka, q3.x, zao0); zbo0 = fma2(hkb, q3.x, zbo0);
                    zao1 = fma2(hka, q3.y, zao1); zbo1 = fma2(hkb, q3.y, zbo1);
                }
            }
            u64 wo_p0 = WO[t * 16 + p0], wo_p1 = WO[t * 16 + p0 + 1];
            u64 h2a0 = lstm_upd<true>(zai0, zaf0, zag0, zao0, ca0, wo_p0, acca);
            u64 h2b0 = lstm_upd<true>(zbi0, zbf0, zbg0, zbo0, cb0, wo_p0, accb);
            u64 h2a1 = lstm_upd<true>(zai1, zaf1, zag1, zao1, ca1, wo_p1, acca);
            u64 h2b1 = lstm_upd<true>(zbi1, zbf1, zbg1, zbo1, cb1, wo_p1, accb);
            if (t < 6) {
                r0[eA] = ca0; r0[eBs] = cb0;
                r1[eA] = ca1; r1[eBs] = cb1;
            }
            float a0, a1, b0v, b1v;
            upk2(h2a0, a0, a1); upk2(h2b0, b0v, b1v);
            hn[4 * c + 0] = pk2(a0, b0v); hn[4 * c + 1] = pk2(a1, b1v);
            upk2(h2a1, a0, a1); upk2(h2b1, b0v, b1v);
            hn[4 * c + 2] = pk2(a0, b0v); hn[4 * c + 3] = pk2(a1, b1v);
        }
#pragma unroll
        for (int u = 0; u < 32; u++) H1[u * NT + tid] = hn[u];
    }

    // y = Σ(acc) + fc_b*Σ_t fc1_w[t] + fc1_b
    float s = 0.0f;
#pragma unroll
    for (int t = 0; t < 7; t++) s += fc1w[t];
    float bias = fcb[0] * s + fc1b[0];

    float alo, ahi; upk2(acca, alo, ahi);
    out[eA] = alo + ahi + bias;
    if (storeB) {
        float blo, bhi; upk2(accb, blo, bhi);
        out[eB] = blo + bhi + bias;
    }
}

extern "C" void kernel_launch(void* const* d_in, const int* in_sizes, int n_in,
                              void* d_out, int out_size) {
    const float* x    = (const float*)d_in[0];
    const float* Wih0 = (const float*)d_in[1];
    const float* Whh0 = (const float*)d_in[2];
    const float* bih0 = (const float*)d_in[3];
    const float* bhh0 = (const float*)d_in[4];
    const float* Wih1 = (const float*)d_in[5];
    const float* Whh1 = (const float*)d_in[6];
    const float* bih1 = (const float*)d_in[7];
    const float* bhh1 = (const float*)d_in[8];
    const float* fcw  = (const float*)d_in[9];
    const float* fcb  = (const float*)d_in[10];
    const float* fc1w = (const float*)d_in[11];
    const float* fc1b = (const float*)d_in[12];
    float* out = (float*)d_out;

    const int B = in_sizes[0] / 7;  // [B, T=7, F=1]

    cudaFuncSetAttribute(lstm_b262144_kernel,
                         cudaFuncAttributeMaxDynamicSharedMemorySize, SMEM_BYTES);

    int grid = (B + EPC - 1) / EPC;
    lstm_b262144_kernel<<<grid, NT, SMEM_BYTES>>>(
        x, Wih0, Whh0, bih0, bhh0, Wih1, Whh1, bih1, bhh1,
        fcw, fcb, fc1w, fc1b, out, B);
}